// round 4
// baseline (speedup 1.0000x reference)
#include <cuda_runtime.h>

// StackedLSTM: B=2048, T=2048, D=H=6, 2 layers, softmax over final h of layer 1.
// Strategy: 8 lanes per batch (lane j<6 owns hidden unit j, computes its 4 gates
// packed as f32x2 pairs (i,f) and (g,o)), weights held in registers, h-state
// broadcast via warp shuffles, layer1(t) and layer0(t+1) software-pipelined.

#define TT 2048
#define BB 2048

typedef unsigned long long u64;

__device__ __forceinline__ u64 pack2(float lo, float hi) {
    u64 r; asm("mov.b64 %0, {%1, %2};" : "=l"(r) : "f"(lo), "f"(hi)); return r;
}
__device__ __forceinline__ u64 pack2s(float v) { return pack2(v, v); }
__device__ __forceinline__ void unpack2(u64 v, float& lo, float& hi) {
    asm("mov.b64 {%0, %1}, %2;" : "=f"(lo), "=f"(hi) : "l"(v));
}
__device__ __forceinline__ u64 ffma2(u64 a, u64 b, u64 c) {
    u64 d; asm("fma.rn.f32x2 %0, %1, %2, %3;" : "=l"(d) : "l"(a), "l"(b), "l"(c));
    return d;
}
__device__ __forceinline__ u64 fadd2(u64 a, u64 b) {
    u64 d; asm("add.rn.f32x2 %0, %1, %2;" : "=l"(d) : "l"(a), "l"(b)); return d;
}

// Accurate fast activations: EX2 + RCP (rel err ~1e-6), overflow-safe.
__device__ __forceinline__ float sigm(float x) {
    float e = __expf(-x);                 // FMUL + MUFU.EX2
    return __fdividef(1.0f, 1.0f + e);    // FADD + MUFU.RCP
}
__device__ __forceinline__ float tanh_(float x) {
    float a = fabsf(x);
    float e = __expf(-2.0f * a);          // in (0,1], never overflows
    float t = __fdividef(1.0f - e, 1.0f + e);
    return copysignf(t, x);
}

struct CellW {
    u64 wif[6], wgo[6];    // input-side weights, packed (gate i|f) and (g|o)
    u64 whif[6], whgo[6];  // recurrent-side weights
    u64 bif, bgo;          // combined biases
};

// One LSTM cell step for this lane's hidden unit.
// xin/hin are 6 pre-packed {v,v} broadcast values of the input/recurrent state.
__device__ __forceinline__ void lstm_cell(const CellW& W, const u64* xin, const u64* hin,
                                          float& h, float& c) {
    u64 aif = W.bif, ago = W.bgo;   // x-side accumulators (with bias)
    u64 hif = 0ull,  hgo = 0ull;    // h-side accumulators (split chains for ILP)
#pragma unroll
    for (int k = 0; k < 6; ++k) {
        aif = ffma2(W.wif[k],  xin[k], aif);
        ago = ffma2(W.wgo[k],  xin[k], ago);
        hif = ffma2(W.whif[k], hin[k], hif);
        hgo = ffma2(W.whgo[k], hin[k], hgo);
    }
    aif = fadd2(aif, hif);
    ago = fadd2(ago, hgo);
    float gi, gf, gg, go;
    unpack2(aif, gi, gf);
    unpack2(ago, gg, go);
    gi = sigm(gi); gf = sigm(gf); gg = tanh_(gg); go = sigm(go);
    c = fmaf(gf, c, gi * gg);
    h = go * tanh_(c);
}

__device__ __forceinline__ void load_x6(const float* __restrict__ p, u64* xp) {
    // p is 8-byte aligned (t*6 floats = t*24 bytes from a 256B-aligned base)
    const float2* q = (const float2*)p;
    float2 a = q[0], b = q[1], c = q[2];
    xp[0] = pack2s(a.x); xp[1] = pack2s(a.y);
    xp[2] = pack2s(b.x); xp[3] = pack2s(b.y);
    xp[4] = pack2s(c.x); xp[5] = pack2s(c.y);
}

__global__ void __launch_bounds__(128, 1)
stacked_lstm_kernel(const float* __restrict__ x,
                    const float* __restrict__ Wi0, const float* __restrict__ Wh0,
                    const float* __restrict__ bi0, const float* __restrict__ bh0,
                    const float* __restrict__ Wi1, const float* __restrict__ Wh1,
                    const float* __restrict__ bi1, const float* __restrict__ bh1,
                    float* __restrict__ out) {
    const int lane = threadIdx.x & 31;
    const int j    = lane & 7;             // hidden-unit index within group (6..7 idle)
    const int jj   = (j < 6) ? j : 5;      // clamp for safe loads on idle lanes
    const int base = lane & ~7;            // shuffle base lane of this 8-lane group
    const int b    = blockIdx.x * 16 + (threadIdx.x >> 3);   // batch index, exact cover

    // ---- Load weights into registers, packed per-k: (row i | row f), (row g | row o).
    // PyTorch gate row order: i=[0:6), f=[6:12), g=[12:18), o=[18:24). D=H=6.
    CellW W0, W1;
#pragma unroll
    for (int k = 0; k < 6; ++k) {
        W0.wif[k]  = pack2(Wi0[(0  + jj) * 6 + k], Wi0[(6  + jj) * 6 + k]);
        W0.wgo[k]  = pack2(Wi0[(12 + jj) * 6 + k], Wi0[(18 + jj) * 6 + k]);
        W0.whif[k] = pack2(Wh0[(0  + jj) * 6 + k], Wh0[(6  + jj) * 6 + k]);
        W0.whgo[k] = pack2(Wh0[(12 + jj) * 6 + k], Wh0[(18 + jj) * 6 + k]);
        W1.wif[k]  = pack2(Wi1[(0  + jj) * 6 + k], Wi1[(6  + jj) * 6 + k]);
        W1.wgo[k]  = pack2(Wi1[(12 + jj) * 6 + k], Wi1[(18 + jj) * 6 + k]);
        W1.whif[k] = pack2(Wh1[(0  + jj) * 6 + k], Wh1[(6  + jj) * 6 + k]);
        W1.whgo[k] = pack2(Wh1[(12 + jj) * 6 + k], Wh1[(18 + jj) * 6 + k]);
    }
    W0.bif = pack2(bi0[jj]      + bh0[jj],      bi0[6  + jj] + bh0[6  + jj]);
    W0.bgo = pack2(bi0[12 + jj] + bh0[12 + jj], bi0[18 + jj] + bh0[18 + jj]);
    W1.bif = pack2(bi1[jj]      + bh1[jj],      bi1[6  + jj] + bh1[6  + jj]);
    W1.bgo = pack2(bi1[12 + jj] + bh1[12 + jj], bi1[18 + jj] + bh1[18 + jj]);

    const float* xb = x + (size_t)b * TT * 6;

    float h0 = 0.f, c0 = 0.f, h1 = 0.f, c1 = 0.f;
    u64 h0g[6], h1g[6];       // broadcast (packed {v,v}) group state
#pragma unroll
    for (int k = 0; k < 6; ++k) { h0g[k] = 0ull; h1g[k] = 0ull; }

    u64 xp[6];

    // ---- Prologue: layer0 step 0
    load_x6(xb, xp);
    lstm_cell(W0, xp, h0g, h0, c0);
#pragma unroll
    for (int k = 0; k < 6; ++k)
        h0g[k] = pack2s(__shfl_sync(0xffffffffu, h0, base + k));

    // ---- Main loop: each iteration runs layer1(t) and layer0(t+1).
    // Both consume the SAME h0g (h0 at step t), so they are independent -> ILP.
    for (int t = 0; t < TT - 1; ++t) {
        // L1 prefetch ~6 steps ahead (covers DRAM latency; 128B line = 5.3 steps)
        {
            int tp = t + 6; if (tp > TT - 1) tp = TT - 1;
            asm volatile("prefetch.global.L1 [%0];" :: "l"(xb + (size_t)tp * 6));
        }
        load_x6(xb + (size_t)(t + 1) * 6, xp);

        lstm_cell(W1, h0g, h1g, h1, c1);   // layer 1, step t
        lstm_cell(W0, xp,  h0g, h0, c0);   // layer 0, step t+1

#pragma unroll
        for (int k = 0; k < 6; ++k)
            h1g[k] = pack2s(__shfl_sync(0xffffffffu, h1, base + k));
#pragma unroll
        for (int k = 0; k < 6; ++k)
            h0g[k] = pack2s(__shfl_sync(0xffffffffu, h0, base + k));
    }

    // ---- Epilogue: layer 1, step T-1
    lstm_cell(W1, h0g, h1g, h1, c1);
#pragma unroll
    for (int k = 0; k < 6; ++k)
        h1g[k] = pack2s(__shfl_sync(0xffffffffu, h1, base + k));

    // ---- Softmax over the 6 hidden units of layer 1 (each lane has all values)
    float hv[6];
#pragma unroll
    for (int k = 0; k < 6; ++k) { float lo, hi; unpack2(h1g[k], lo, hi); hv[k] = lo; (void)hi; }
    float m = hv[0];
#pragma unroll
    for (int k = 1; k < 6; ++k) m = fmaxf(m, hv[k]);
    float s = 0.f, ev[6];
#pragma unroll
    for (int k = 0; k < 6; ++k) { ev[k] = __expf(hv[k] - m); s += ev[k]; }
    if (j < 6)
        out[(size_t)b * 6 + j] = __fdividef(ev[j], s);
}

extern "C" void kernel_launch(void* const* d_in, const int* in_sizes, int n_in,
                              void* d_out, int out_size) {
    (void)in_sizes; (void)n_in; (void)out_size;
    const float* x   = (const float*)d_in[0];
    const float* Wi0 = (const float*)d_in[1];
    const float* Wh0 = (const float*)d_in[2];
    const float* bi0 = (const float*)d_in[3];
    const float* bh0 = (const float*)d_in[4];
    const float* Wi1 = (const float*)d_in[5];
    const float* Wh1 = (const float*)d_in[6];
    const float* bi1 = (const float*)d_in[7];
    const float* bh1 = (const float*)d_in[8];
    float* out = (float*)d_out;

    // 2048 batches * 8 lanes = 16384 threads = 128 blocks x 128 threads.
    // blockDim=128 guarantees the 4 warps land on all 4 SMSPs per SM.
    stacked_lstm_kernel<<<128, 128>>>(x, Wi0, Wh0, bi0, bh0, Wi1, Wh1, bi1, bh1, out);
}

// round 5
// speedup vs baseline: 1.4429x; 1.4429x over previous
#include <cuda_runtime.h>

// StackedLSTM: B=2048, T=2048, D=H=6, 2 layers, softmax over final h of layer 1.
// Latency-optimized serial scan: 8 lanes per batch (lane j<6 owns hidden unit j,
// 4 gates packed as f32x2 pairs (i,f),(g,o)), weights in registers, h broadcast
// via shuffles, layer1(t) & layer0(t+1) pipelined, MUFU.TANH activations.

#define TT 2048

typedef unsigned long long u64;

__device__ __forceinline__ u64 pack2(float lo, float hi) {
    u64 r; asm("mov.b64 %0, {%1, %2};" : "=l"(r) : "f"(lo), "f"(hi)); return r;
}
__device__ __forceinline__ u64 pack2s(float v) { return pack2(v, v); }
__device__ __forceinline__ void unpack2(u64 v, float& lo, float& hi) {
    asm("mov.b64 {%0, %1}, %2;" : "=f"(lo), "=f"(hi) : "l"(v));
}
__device__ __forceinline__ u64 ffma2(u64 a, u64 b, u64 c) {
    u64 d; asm("fma.rn.f32x2 %0, %1, %2, %3;" : "=l"(d) : "l"(a), "l"(b), "l"(c));
    return d;
}
__device__ __forceinline__ u64 fadd2(u64 a, u64 b) {
    u64 d; asm("add.rn.f32x2 %0, %1, %2;" : "=l"(d) : "l"(a), "l"(b)); return d;
}

// MUFU.TANH: 1 instruction, lat 16, abs err ~1e-4.
__device__ __forceinline__ float tanh_f(float x) {
    float y; asm("tanh.approx.f32 %0, %1;" : "=f"(y) : "f"(x)); return y;
}
// sigmoid(x) = 0.5 + 0.5*tanh(0.5x): FMUL + MUFU.TANH + FFMA, lat ~24.
__device__ __forceinline__ float sigm(float x) {
    return fmaf(tanh_f(0.5f * x), 0.5f, 0.5f);
}

struct CellW {
    u64 wif[6], wgo[6];    // input-side weights, packed (gate i|f) and (g|o)
    u64 whif[6], whgo[6];  // recurrent-side weights
    u64 bif, bgo;          // combined biases
};

// One LSTM cell step for this lane's hidden unit.
// xin/hin: 6 pre-packed {v,v} broadcast values. Tree-reduced dot products.
__device__ __forceinline__ void lstm_cell(const CellW& W, const u64* xin, const u64* hin,
                                          float& h, float& c) {
    // 8 independent 3-deep chains (latency 12) then 3-level combine.
    u64 aif0 = W.bif, aif1 = 0ull, ago0 = W.bgo, ago1 = 0ull;
    u64 hif0 = 0ull, hif1 = 0ull, hgo0 = 0ull, hgo1 = 0ull;
#pragma unroll
    for (int k = 0; k < 3; ++k) {
        aif0 = ffma2(W.wif[k],      xin[k],     aif0);
        aif1 = ffma2(W.wif[k + 3],  xin[k + 3], aif1);
        ago0 = ffma2(W.wgo[k],      xin[k],     ago0);
        ago1 = ffma2(W.wgo[k + 3],  xin[k + 3], ago1);
        hif0 = ffma2(W.whif[k],     hin[k],     hif0);
        hif1 = ffma2(W.whif[k + 3], hin[k + 3], hif1);
        hgo0 = ffma2(W.whgo[k],     hin[k],     hgo0);
        hgo1 = ffma2(W.whgo[k + 3], hin[k + 3], hgo1);
    }
    u64 aif = fadd2(fadd2(aif0, aif1), fadd2(hif0, hif1));
    u64 ago = fadd2(fadd2(ago0, ago1), fadd2(hgo0, hgo1));
    float gi, gf, gg, go;
    unpack2(aif, gi, gf);
    unpack2(ago, gg, go);
    gi = sigm(gi); gf = sigm(gf); gg = tanh_f(gg); go = sigm(go);
    c = fmaf(gf, c, gi * gg);
    h = go * tanh_f(c);
}

__device__ __forceinline__ void load_x6(const float* __restrict__ p, u64* xp) {
    const float2* q = (const float2*)p;   // 8B aligned: t*24B from 256B-aligned base
    float2 a = q[0], b = q[1], c = q[2];
    xp[0] = pack2s(a.x); xp[1] = pack2s(a.y);
    xp[2] = pack2s(b.x); xp[3] = pack2s(b.y);
    xp[4] = pack2s(c.x); xp[5] = pack2s(c.y);
}

__global__ void __launch_bounds__(128, 1)
stacked_lstm_kernel(const float* __restrict__ x,
                    const float* __restrict__ Wi0, const float* __restrict__ Wh0,
                    const float* __restrict__ bi0, const float* __restrict__ bh0,
                    const float* __restrict__ Wi1, const float* __restrict__ Wh1,
                    const float* __restrict__ bi1, const float* __restrict__ bh1,
                    float* __restrict__ out) {
    const int lane = threadIdx.x & 31;
    const int j    = lane & 7;             // hidden unit within 8-lane group (6,7 idle)
    const int jj   = (j < 6) ? j : 5;      // clamp for safe weight loads on idle lanes
    const int base = lane & ~7;            // group's base lane for shuffles
    const int b    = blockIdx.x * 16 + (threadIdx.x >> 3);   // batch index

    // Weights into registers; PyTorch gate rows: i=[0:6) f=[6:12) g=[12:18) o=[18:24).
    CellW W0, W1;
#pragma unroll
    for (int k = 0; k < 6; ++k) {
        W0.wif[k]  = pack2(Wi0[(0  + jj) * 6 + k], Wi0[(6  + jj) * 6 + k]);
        W0.wgo[k]  = pack2(Wi0[(12 + jj) * 6 + k], Wi0[(18 + jj) * 6 + k]);
        W0.whif[k] = pack2(Wh0[(0  + jj) * 6 + k], Wh0[(6  + jj) * 6 + k]);
        W0.whgo[k] = pack2(Wh0[(12 + jj) * 6 + k], Wh0[(18 + jj) * 6 + k]);
        W1.wif[k]  = pack2(Wi1[(0  + jj) * 6 + k], Wi1[(6  + jj) * 6 + k]);
        W1.wgo[k]  = pack2(Wi1[(12 + jj) * 6 + k], Wi1[(18 + jj) * 6 + k]);
        W1.whif[k] = pack2(Wh1[(0  + jj) * 6 + k], Wh1[(6  + jj) * 6 + k]);
        W1.whgo[k] = pack2(Wh1[(12 + jj) * 6 + k], Wh1[(18 + jj) * 6 + k]);
    }
    W0.bif = pack2(bi0[jj]      + bh0[jj],      bi0[6  + jj] + bh0[6  + jj]);
    W0.bgo = pack2(bi0[12 + jj] + bh0[12 + jj], bi0[18 + jj] + bh0[18 + jj]);
    W1.bif = pack2(bi1[jj]      + bh1[jj],      bi1[6  + jj] + bh1[6  + jj]);
    W1.bgo = pack2(bi1[12 + jj] + bh1[12 + jj], bi1[18 + jj] + bh1[18 + jj]);

    const float* xb = x + (size_t)b * TT * 6;

    float h0 = 0.f, c0 = 0.f, h1 = 0.f, c1 = 0.f;
    u64 h0g[6], h1g[6];
#pragma unroll
    for (int k = 0; k < 6; ++k) { h0g[k] = 0ull; h1g[k] = 0ull; }

    u64 xp[6];

    // Prologue: layer0 step 0.
    load_x6(xb, xp);
    lstm_cell(W0, xp, h0g, h0, c0);
#pragma unroll
    for (int k = 0; k < 6; ++k)
        h0g[k] = pack2s(__shfl_sync(0xffffffffu, h0, base + k));

    // Main loop: layer1(t) and layer0(t+1) share h0g -> independent -> ILP.
    for (int t = 0; t < TT - 1; ++t) {
        {   // L1 prefetch ~6 steps ahead (128B line = 5.3 steps)
            int tp = t + 6; if (tp > TT - 1) tp = TT - 1;
            asm volatile("prefetch.global.L1 [%0];" :: "l"(xb + (size_t)tp * 6));
        }
        load_x6(xb + (size_t)(t + 1) * 6, xp);

        lstm_cell(W1, h0g, h1g, h1, c1);   // layer 1, step t
        lstm_cell(W0, xp,  h0g, h0, c0);   // layer 0, step t+1

#pragma unroll
        for (int k = 0; k < 6; ++k)
            h1g[k] = pack2s(__shfl_sync(0xffffffffu, h1, base + k));
#pragma unroll
        for (int k = 0; k < 6; ++k)
            h0g[k] = pack2s(__shfl_sync(0xffffffffu, h0, base + k));
    }

    // Epilogue: layer 1, step T-1.
    lstm_cell(W1, h0g, h1g, h1, c1);
#pragma unroll
    for (int k = 0; k < 6; ++k)
        h1g[k] = pack2s(__shfl_sync(0xffffffffu, h1, base + k));

    // Softmax over the 6 layer-1 hidden units (every lane holds all 6).
    float hv[6];
#pragma unroll
    for (int k = 0; k < 6; ++k) { float lo, hi; unpack2(h1g[k], lo, hi); hv[k] = lo; (void)hi; }
    float m = hv[0];
#pragma unroll
    for (int k = 1; k < 6; ++k) m = fmaxf(m, hv[k]);
    float s = 0.f, ev[6];
#pragma unroll
    for (int k = 0; k < 6; ++k) { ev[k] = __expf(hv[k] - m); s += ev[k]; }
    if (j < 6)
        out[(size_t)b * 6 + j] = __fdividef(ev[j], s);
}

extern "C" void kernel_launch(void* const* d_in, const int* in_sizes, int n_in,
                              void* d_out, int out_size) {
    (void)in_sizes; (void)n_in; (void)out_size;
    const float* x   = (const float*)d_in[0];
    const float* Wi0 = (const float*)d_in[1];
    const float* Wh0 = (const float*)d_in[2];
    const float* bi0 = (const float*)d_in[3];
    const float* bh0 = (const float*)d_in[4];
    const float* Wi1 = (const float*)d_in[5];
    const float* Wh1 = (const float*)d_in[6];
    const float* bi1 = (const float*)d_in[7];
    const float* bh1 = (const float*)d_in[8];
    float* out = (float*)d_out;

    // 2048 batches * 8 lanes = 16384 threads = 128 blocks x 128 threads.
    // 1 warp/SMSP: a latency-bound serial scan wants zero co-residency contention.
    stacked_lstm_kernel<<<128, 128>>>(x, Wi0, Wh0, bi0, bh0, Wi1, Wh1, bi1, bh1, out);
}

// round 6
// speedup vs baseline: 2.0514x; 1.4217x over previous
#include <cuda_runtime.h>

// StackedLSTM: B=2048, T=2048, D=H=6, 2 layers, softmax over final h of layer 1.
// Lane-split design: 16 lanes per batch. Lanes 0-7 run layer 0 (unit j = lane&7),
// lanes 8-15 run layer 1. h0 flows to layer-1 lanes via warp shuffles with a
// 1-step skew, so each lane runs ONE LSTM cell per iteration. Weights live in
// registers packed as f32x2 gate pairs (i,f),(g,o). x is double-buffered in
// registers 4 timesteps ahead (6x float4 per block, 16B aligned).

#define TT 2048

typedef unsigned long long u64;

__device__ __forceinline__ u64 pack2(float lo, float hi) {
    u64 r; asm("mov.b64 %0, {%1, %2};" : "=l"(r) : "f"(lo), "f"(hi)); return r;
}
__device__ __forceinline__ u64 pack2s(float v) { return pack2(v, v); }
__device__ __forceinline__ void unpack2(u64 v, float& lo, float& hi) {
    asm("mov.b64 {%0, %1}, %2;" : "=f"(lo), "=f"(hi) : "l"(v));
}
__device__ __forceinline__ u64 ffma2(u64 a, u64 b, u64 c) {
    u64 d; asm("fma.rn.f32x2 %0, %1, %2, %3;" : "=l"(d) : "l"(a), "l"(b), "l"(c));
    return d;
}
__device__ __forceinline__ u64 fadd2(u64 a, u64 b) {
    u64 d; asm("add.rn.f32x2 %0, %1, %2;" : "=l"(d) : "l"(a), "l"(b)); return d;
}

// MUFU.TANH: 1 instruction, abs err ~1e-4 (validated rel_err 8e-7 end to end).
__device__ __forceinline__ float tanh_f(float x) {
    float y; asm("tanh.approx.f32 %0, %1;" : "=f"(y) : "f"(x)); return y;
}
// sigmoid(x) = 0.5 + 0.5*tanh(0.5x)
__device__ __forceinline__ float sigm(float x) {
    return fmaf(tanh_f(0.5f * x), 0.5f, 0.5f);
}

struct CellW {
    u64 wif[6], wgo[6];    // input-side weights, packed (gate i|f) and (g|o)
    u64 whif[6], whgo[6];  // recurrent-side weights
    u64 bif, bgo;          // combined biases
};

// One LSTM cell step for this lane's hidden unit. xin/hin: packed {v,v} vectors.
__device__ __forceinline__ void lstm_cell(const CellW& W, const u64* xin, const u64* hin,
                                          float& h, float& c) {
    u64 aif0 = W.bif, aif1 = 0ull, ago0 = W.bgo, ago1 = 0ull;
    u64 hif0 = 0ull, hif1 = 0ull, hgo0 = 0ull, hgo1 = 0ull;
#pragma unroll
    for (int k = 0; k < 3; ++k) {
        aif0 = ffma2(W.wif[k],      xin[k],     aif0);
        aif1 = ffma2(W.wif[k + 3],  xin[k + 3], aif1);
        ago0 = ffma2(W.wgo[k],      xin[k],     ago0);
        ago1 = ffma2(W.wgo[k + 3],  xin[k + 3], ago1);
        hif0 = ffma2(W.whif[k],     hin[k],     hif0);
        hif1 = ffma2(W.whif[k + 3], hin[k + 3], hif1);
        hgo0 = ffma2(W.whgo[k],     hin[k],     hgo0);
        hgo1 = ffma2(W.whgo[k + 3], hin[k + 3], hgo1);
    }
    u64 aif = fadd2(fadd2(aif0, aif1), fadd2(hif0, hif1));
    u64 ago = fadd2(fadd2(ago0, ago1), fadd2(hgo0, hgo1));
    float gi, gf, gg, go;
    unpack2(aif, gi, gf);
    unpack2(ago, gg, go);
    gi = sigm(gi); gf = sigm(gf); gg = tanh_f(gg); go = sigm(go);
    c = fmaf(gf, c, gi * gg);
    h = go * tanh_f(c);
}

// One fused iteration: all lanes shuffle state, select input (x for L0 lanes,
// h0 broadcast for L1 lanes), run one cell.
__device__ __forceinline__ void iter_step(const CellW& W, bool isL1,
                                          int rbase, int gbase,
                                          const float* xs, float& h, float& c) {
    u64 rg[6], in[6];
#pragma unroll
    for (int k = 0; k < 6; ++k) {
        float rv = __shfl_sync(0xffffffffu, h, rbase + k);   // own-layer recurrence
        float hv = __shfl_sync(0xffffffffu, h, gbase + k);   // h0 (for L1 input)
        float iv = isL1 ? hv : xs[k];
        rg[k] = pack2s(rv);
        in[k] = pack2s(iv);
    }
    lstm_cell(W, in, rg, h, c);
}

// Run 4 timesteps from a 6x float4 register block (24 floats = 4 steps of x).
template <bool ZEROFIX>
__device__ __forceinline__ void steps4(const CellW& W, bool isL1, int rbase, int gbase,
                                       const float4* buf, float& h, float& c) {
    const float* bp = (const float*)buf;
#pragma unroll
    for (int s = 0; s < 4; ++s) {
        float xs[6];
#pragma unroll
        for (int k = 0; k < 6; ++k) xs[k] = bp[6 * s + k];
        iter_step(W, isL1, rbase, gbase, xs, h, c);
        if (ZEROFIX && s == 0) {
            // iteration 0's layer-1 step is spurious (no layer-1 time -1): reset.
            if (isL1) { h = 0.f; c = 0.f; }
        }
    }
}

__device__ __forceinline__ void loadblk(const float* __restrict__ xb, int m, float4* buf) {
    const float4* p = (const float4*)(xb + 24 * m);   // 96B blocks, 16B aligned
#pragma unroll
    for (int i = 0; i < 6; ++i) buf[i] = p[i];
}

__global__ void __launch_bounds__(256, 1)
stacked_lstm_kernel(const float* __restrict__ x,
                    const float* __restrict__ Wi0, const float* __restrict__ Wh0,
                    const float* __restrict__ bi0, const float* __restrict__ bh0,
                    const float* __restrict__ Wi1, const float* __restrict__ Wh1,
                    const float* __restrict__ bi1, const float* __restrict__ bh1,
                    float* __restrict__ out) {
    const int lane  = threadIdx.x & 31;
    const bool isL1 = (lane & 8) != 0;     // lanes 8-15 (and 24-31) run layer 1
    const int j     = lane & 7;            // hidden unit within layer-group (6,7 idle)
    const int jj    = (j < 6) ? j : 5;     // clamp for safe weight loads
    const int rbase = lane & ~7;           // own-layer shuffle base
    const int gbase = lane & ~15;          // group base = layer-0 lanes
    const int b     = (blockIdx.x * blockDim.x + threadIdx.x) >> 4;   // batch

    // Per-lane weight set: layer 0 or layer 1.
    const float* Wi = isL1 ? Wi1 : Wi0;
    const float* Wh = isL1 ? Wh1 : Wh0;
    const float* bi = isL1 ? bi1 : bi0;
    const float* bh = isL1 ? bh1 : bh0;

    // PyTorch gate rows: i=[0:6) f=[6:12) g=[12:18) o=[18:24). D=H=6.
    CellW W;
#pragma unroll
    for (int k = 0; k < 6; ++k) {
        W.wif[k]  = pack2(Wi[(0  + jj) * 6 + k], Wi[(6  + jj) * 6 + k]);
        W.wgo[k]  = pack2(Wi[(12 + jj) * 6 + k], Wi[(18 + jj) * 6 + k]);
        W.whif[k] = pack2(Wh[(0  + jj) * 6 + k], Wh[(6  + jj) * 6 + k]);
        W.whgo[k] = pack2(Wh[(12 + jj) * 6 + k], Wh[(18 + jj) * 6 + k]);
    }
    W.bif = pack2(bi[jj]      + bh[jj],      bi[6  + jj] + bh[6  + jj]);
    W.bgo = pack2(bi[12 + jj] + bh[12 + jj], bi[18 + jj] + bh[18 + jj]);

    const float* xb = x + (size_t)b * TT * 6;

    float h = 0.f, c = 0.f;

    // x double buffer: each block = 4 timesteps = 6 float4.
    float4 bufA[6], bufB[6];

    loadblk(xb, 0, bufB);
    loadblk(xb, 1, bufA);

    // Block 0 (steps 0-3), with layer-1 zero-fix after step 0.
    steps4<true>(W, isL1, rbase, gbase, bufB, h, c);

    // Pair-unrolled main loop: blocks 1..510 (255 pairs). Each block's loads are
    // issued one full block (4 iterations) before consumption.
#pragma unroll 1
    for (int m = 1; m < 511; m += 2) {
        loadblk(xb, m + 1, bufB);
        steps4<false>(W, isL1, rbase, gbase, bufA, h, c);   // block m
        loadblk(xb, m + 2, bufA);                           // m+2 <= 511
        steps4<false>(W, isL1, rbase, gbase, bufB, h, c);   // block m+1
    }
    // Block 511 (steps 2044-2047).
    steps4<false>(W, isL1, rbase, gbase, bufA, h, c);

    // Epilogue iteration n=2048: layer 1 consumes h0(2047). L0 input = 0 (unused).
    {
        float zs[6] = {0.f, 0.f, 0.f, 0.f, 0.f, 0.f};
        iter_step(W, isL1, rbase, gbase, zs, h, c);
    }

    // Gather final layer-1 h (lanes gbase+8+k) and softmax.
    float hv[6];
#pragma unroll
    for (int k = 0; k < 6; ++k)
        hv[k] = __shfl_sync(0xffffffffu, h, gbase + 8 + k);
    float m = hv[0];
#pragma unroll
    for (int k = 1; k < 6; ++k) m = fmaxf(m, hv[k]);
    float s = 0.f, ev[6];
#pragma unroll
    for (int k = 0; k < 6; ++k) { ev[k] = __expf(hv[k] - m); s += ev[k]; }
    if (isL1 && j < 6)
        out[(size_t)b * 6 + j] = __fdividef(ev[j], s);
}

extern "C" void kernel_launch(void* const* d_in, const int* in_sizes, int n_in,
                              void* d_out, int out_size) {
    (void)in_sizes; (void)n_in; (void)out_size;
    const float* x   = (const float*)d_in[0];
    const float* Wi0 = (const float*)d_in[1];
    const float* Wh0 = (const float*)d_in[2];
    const float* bi0 = (const float*)d_in[3];
    const float* bh0 = (const float*)d_in[4];
    const float* Wi1 = (const float*)d_in[5];
    const float* Wh1 = (const float*)d_in[6];
    const float* bi1 = (const float*)d_in[7];
    const float* bh1 = (const float*)d_in[8];
    float* out = (float*)d_out;

    // 2048 batches * 16 lanes = 32768 threads = 128 blocks x 256 threads:
    // exactly 1 block/SM on 128 SMs, uniform 2 warps/SMSP.
    stacked_lstm_kernel<<<128, 256>>>(x, Wi0, Wh0, bi0, bh0, Wi1, Wh1, bi1, bh1, out);
}

// round 7
// speedup vs baseline: 2.2795x; 1.1112x over previous
#include <cuda_runtime.h>

// StackedLSTM: B=2048, T=2048, D=H=6, 2 layers, softmax over final h of layer 1.
// 16 lanes per batch: lanes 0-7 run layer 0 (unit j = lane&7), lanes 8-15 layer 1
// (1-step skew). State exchange via double-buffered warp-synchronous shared
// memory (vector LDS, no shuffles). f32x2 FFMA with k-pair packing; weights in
// registers with sigmoid 0.5-prescale folded in. x double-buffered as ulonglong2.

#define TT 2048

typedef unsigned long long u64;
typedef ulonglong2 u64x2;

__device__ __forceinline__ u64 pack2(float lo, float hi) {
    u64 r; asm("mov.b64 %0, {%1, %2};" : "=l"(r) : "f"(lo), "f"(hi)); return r;
}
__device__ __forceinline__ void unpack2(u64 v, float& lo, float& hi) {
    asm("mov.b64 {%0, %1}, %2;" : "=f"(lo), "=f"(hi) : "l"(v));
}
__device__ __forceinline__ u64 ffma2(u64 a, u64 b, u64 c) {
    u64 d; asm("fma.rn.f32x2 %0, %1, %2, %3;" : "=l"(d) : "l"(a), "l"(b), "l"(c));
    return d;
}
__device__ __forceinline__ u64 fadd2(u64 a, u64 b) {
    u64 d; asm("add.rn.f32x2 %0, %1, %2;" : "=l"(d) : "l"(a), "l"(b)); return d;
}
__device__ __forceinline__ float tanh_f(float x) {
    float y; asm("tanh.approx.f32 %0, %1;" : "=f"(y) : "f"(x)); return y;
}

struct CellW {
    u64 wx[4][3];   // input-side weight k-pairs per gate (i,f,g,o), prescaled
    u64 wh[4][3];   // recurrent-side weight k-pairs
    u64 b[4];       // bias in lo half, 0 in hi half
};

// One LSTM cell: in[3]/rg[3] are k-pair packed {v2k, v2k+1} input/recurrent vecs.
__device__ __forceinline__ void cell(const CellW& W, const u64* in, const u64* rg,
                                     float& h, float& c) {
    float g[4];
#pragma unroll
    for (int q = 0; q < 4; ++q) {
        u64 ax = ffma2(W.wx[q][0], in[0], W.b[q]);
        ax     = ffma2(W.wx[q][1], in[1], ax);
        ax     = ffma2(W.wx[q][2], in[2], ax);
        u64 ah = ffma2(W.wh[q][0], rg[0], 0ull);
        ah     = ffma2(W.wh[q][1], rg[1], ah);
        ah     = ffma2(W.wh[q][2], rg[2], ah);
        u64 s2 = fadd2(ax, ah);
        float lo, hi; unpack2(s2, lo, hi);
        g[q] = lo + hi;
    }
    // sigmoid gates were prescaled by 0.5 in the weights: sig = .5 + .5*tanh(g^)
    float gi = fmaf(tanh_f(g[0]), 0.5f, 0.5f);
    float gf = fmaf(tanh_f(g[1]), 0.5f, 0.5f);
    float gg = tanh_f(g[2]);
    float go = fmaf(tanh_f(g[3]), 0.5f, 0.5f);
    c = fmaf(gf, c, gi * gg);
    h = go * tanh_f(c);
}

// One fused iteration. rg_rd: own-layer recurrent state (6 floats), h0_rd: layer-0
// state (input for L1 lanes), wslot: this lane's write slot in the other buffer.
template <bool ZF>
__device__ __forceinline__ void iter(const CellW& W, bool isL1,
                                     const float* rg_rd, const float* h0_rd,
                                     float* wslot, const u64* xp,
                                     float& h, float& c) {
    __syncwarp();
    u64x2 a = *(const u64x2*)h0_rd;  u64 a2 = ((const u64*)h0_rd)[2];
    u64x2 r = *(const u64x2*)rg_rd;  u64 r2 = ((const u64*)rg_rd)[2];
    u64 in[3] = { isL1 ? a.x : xp[0], isL1 ? a.y : xp[1], isL1 ? a2 : xp[2] };
    u64 rg[3] = { r.x, r.y, r2 };
    cell(W, in, rg, h, c);
    if (ZF && isL1) { h = 0.f; c = 0.f; }   // iteration 0: layer-1 step is spurious
    *wslot = h;
}

// 4 timesteps from one x block (12 u64 = 24 floats). Read parity alternates 0,1,0,1.
template <bool ZF>
__device__ __forceinline__ void steps4(const CellW& W, bool isL1,
                                       const float* rg0, const float* rg1,
                                       const float* h00, const float* h01,
                                       float* w0, float* w1,
                                       const u64* u, float& h, float& c) {
    iter<ZF>   (W, isL1, rg0, h00, w1, u + 0, h, c);
    iter<false>(W, isL1, rg1, h01, w0, u + 3, h, c);
    iter<false>(W, isL1, rg0, h00, w1, u + 6, h, c);
    iter<false>(W, isL1, rg1, h01, w0, u + 9, h, c);
}

__device__ __forceinline__ void loadblk(const float* __restrict__ xb, int m, u64* u) {
    const u64x2* p = (const u64x2*)(xb + 24 * m);   // 96B block, 16B aligned
#pragma unroll
    for (int i = 0; i < 6; ++i) { u64x2 v = p[i]; u[2 * i] = v.x; u[2 * i + 1] = v.y; }
}

__global__ void __launch_bounds__(256, 1)
stacked_lstm_kernel(const float* __restrict__ x,
                    const float* __restrict__ Wi0, const float* __restrict__ Wh0,
                    const float* __restrict__ bi0, const float* __restrict__ bh0,
                    const float* __restrict__ Wi1, const float* __restrict__ Wh1,
                    const float* __restrict__ bi1, const float* __restrict__ bh1,
                    float* __restrict__ out) {
    const int lane  = threadIdx.x & 31;
    const bool isL1 = (lane & 8) != 0;      // lanes 8-15 / 24-31 run layer 1
    const int j     = lane & 7;             // hidden unit (6,7 idle padding lanes)
    const int jj    = (j < 6) ? j : 5;      // clamp for safe weight loads
    const int b     = (blockIdx.x * blockDim.x + threadIdx.x) >> 4;   // batch

    // Per-lane weight set.
    const float* Wi = isL1 ? Wi1 : Wi0;
    const float* Wh = isL1 ? Wh1 : Wh0;
    const float* bi = isL1 ? bi1 : bi0;
    const float* bh = isL1 ? bh1 : bh0;

    // PyTorch gate rows: i=[0:6) f=[6:12) g=[12:18) o=[18:24).
    // Sigmoid gates (i,f,o) prescaled by 0.5 so sig = .5 + .5*tanh(prescaled).
    CellW W;
    const int   goff[4] = {0, 6, 12, 18};
    const float gscl[4] = {0.5f, 0.5f, 1.0f, 0.5f};
#pragma unroll
    for (int q = 0; q < 4; ++q) {
        const int   r = goff[q] + jj;
        const float s = gscl[q];
#pragma unroll
        for (int p = 0; p < 3; ++p) {
            W.wx[q][p] = pack2(s * Wi[r * 6 + 2 * p], s * Wi[r * 6 + 2 * p + 1]);
            W.wh[q][p] = pack2(s * Wh[r * 6 + 2 * p], s * Wh[r * 6 + 2 * p + 1]);
        }
        W.b[q] = pack2(s * (bi[r] + bh[r]), 0.f);
    }

    // Shared state: 2 parity buffers x 16 groups x 16 floats (h0 at [0:6), h1 at [8:14)).
    __shared__ __align__(16) float sbuf[2][16][16];
    const int wg   = threadIdx.x >> 4;
    float* b0 = &sbuf[0][wg][0];
    float* b1 = &sbuf[1][wg][0];
    const int ro   = isL1 ? 8 : 0;
    const int slot = ro + j;
    const float* rg0 = b0 + ro;  const float* rg1 = b1 + ro;
    const float* h00 = b0;       const float* h01 = b1;
    float* w0 = b0 + slot;       float* w1 = b1 + slot;

    // Zero both buffers (each 16-lane group zeroes its own 16 slots).
    b0[lane & 15] = 0.f;
    b1[lane & 15] = 0.f;

    const float* xb = x + (size_t)b * TT * 6;

    float h = 0.f, c = 0.f;

    u64 A[12], B[12];                // x double buffer: 4 timesteps per block
    loadblk(xb, 0, B);
    loadblk(xb, 1, A);

    steps4<true>(W, isL1, rg0, rg1, h00, h01, w0, w1, B, h, c);   // block 0

#pragma unroll 1
    for (int m = 1; m < 511; m += 2) {
        loadblk(xb, m + 1, B);
        steps4<false>(W, isL1, rg0, rg1, h00, h01, w0, w1, A, h, c);   // block m
        loadblk(xb, m + 2, A);
        steps4<false>(W, isL1, rg0, rg1, h00, h01, w0, w1, B, h, c);   // block m+1
    }
    steps4<false>(W, isL1, rg0, rg1, h00, h01, w0, w1, A, h, c);       // block 511

    // Epilogue iteration 2048 (even parity: rd buf0, wr buf1): layer 1 consumes
    // h0(2047). Layer-0 input is zero (result discarded).
    {
        u64 z[3] = {0ull, 0ull, 0ull};
        iter<false>(W, isL1, rg0, h00, w1, z, h, c);
    }

    // Final h1 now lives in buf1 slots [8:14). Softmax over the 6 values.
    __syncwarp();
    float hv[6];
#pragma unroll
    for (int k = 0; k < 6; ++k) hv[k] = b1[8 + k];
    float m = hv[0];
#pragma unroll
    for (int k = 1; k < 6; ++k) m = fmaxf(m, hv[k]);
    float s = 0.f, ev[6];
#pragma unroll
    for (int k = 0; k < 6; ++k) { ev[k] = __expf(hv[k] - m); s += ev[k]; }
    if (isL1 && j < 6)
        out[(size_t)b * 6 + j] = __fdividef(ev[j], s);
}

extern "C" void kernel_launch(void* const* d_in, const int* in_sizes, int n_in,
                              void* d_out, int out_size) {
    (void)in_sizes; (void)n_in; (void)out_size;
    const float* x   = (const float*)d_in[0];
    const float* Wi0 = (const float*)d_in[1];
    const float* Wh0 = (const float*)d_in[2];
    const float* bi0 = (const float*)d_in[3];
    const float* bh0 = (const float*)d_in[4];
    const float* Wi1 = (const float*)d_in[5];
    const float* Wh1 = (const float*)d_in[6];
    const float* bi1 = (const float*)d_in[7];
    const float* bh1 = (const float*)d_in[8];
    float* out = (float*)d_out;

    // 2048 batches * 16 lanes = 32768 threads = 128 blocks x 256 threads:
    // 1 block/SM on 128 SMs, uniform 2 warps/SMSP.
    stacked_lstm_kernel<<<128, 256>>>(x, Wi0, Wh0, bi0, bh0, Wi1, Wh1, bi1, bh1, out);
}